// round 5
// baseline (speedup 1.0000x reference)
#include <cuda_runtime.h>

#define HH 512
#define WW 512
#define CC 64
#define RROWS 16

__device__ float g_scales[192];

__global__ void softplus_kernel(const float* __restrict__ D) {
    int i = threadIdx.x;
    if (i < 192) {
        float x = D[i];
        g_scales[i] = (x > 20.0f) ? x : log1pf(expf(x));
    }
}

__device__ __forceinline__ float4 ld4(const float* __restrict__ p) {
    return *reinterpret_cast<const float4*>(p);
}
__device__ __forceinline__ float4 f4all(float v) {
    return make_float4(v, v, v, v);
}

// ---------------- interior kernel: no vertical clamping ----------------
// covers y0 = 16 .. 480 (blockIdx.y 0..29); all y-d / y+d in range.
__global__ __launch_bounds__(128, 9) void lap_interior(const float* __restrict__ u,
                                                       float* __restrict__ out) {
    const int lane = threadIdx.x;
    const int span = threadIdx.y;
    const int x0   = (span << 7) + (lane << 2);
    const int y0   = (blockIdx.y + 1) * RROWS;
    const int img  = blockIdx.z;
    const int ch   = img & (CC - 1);

    const float* __restrict__ base = u + (size_t)img * (HH * WW);
    float* __restrict__ ob = out + (size_t)img * (HH * WW);

    const float s0 = g_scales[ch];
    const float s1 = g_scales[64 + ch];
    const float s2 = g_scales[128 + ch];
    const float sm4 = -4.0f * (s0 + s1 + s2);
    const unsigned m = 0xFFFFFFFFu;

    // single strength-reduced pointer; all taps are immediate offsets
    const float* __restrict__ pc = base + y0 * WW + x0;
    float* __restrict__ po = ob + y0 * WW + x0;

    // 3-row rolling window
    float4 w0 = ld4(pc - WW);
    float4 w1 = ld4(pc);
    float4 w2 = ld4(pc + WW);

#pragma unroll
    for (int t = 0; t < RROWS; t++) {
        const float* __restrict__ p = pc + t * WW;

        const float4 u4v = ld4(p - 4 * WW);
        const float4 d4v = ld4(p + 4 * WW);
        const float4 u16 = ld4(p - 16 * WW);
        const float4 d16 = ld4(p + 16 * WW);

        const float4 c  = w1;
        const float4 u1 = w0;
        const float4 d1 = w2;

        // d=16 horizontal: aligned clamped loads (clamp only at image x-edges)
        const float4 l16 = (x0 >= 16)     ? ld4(p - 16) : f4all(p[-x0]);
        const float4 r16 = (x0 + 16 < WW) ? ld4(p + 16) : f4all(p[WW - 1 - x0]);

        // d=4 horizontal via neighbor-lane shuffles
        float4 l4, r4;
        l4.x = __shfl_up_sync(m, c.x, 1);
        l4.y = __shfl_up_sync(m, c.y, 1);
        l4.z = __shfl_up_sync(m, c.z, 1);
        l4.w = __shfl_up_sync(m, c.w, 1);
        r4.x = __shfl_down_sync(m, c.x, 1);
        r4.y = __shfl_down_sync(m, c.y, 1);
        r4.z = __shfl_down_sync(m, c.z, 1);
        r4.w = __shfl_down_sync(m, c.w, 1);

        float l1 = l4.w;
        float r1 = r4.x;
        if (lane == 0) {
            l1 = (x0 > 0) ? p[-1] : c.x;
            l4 = (x0 >= 4) ? ld4(p - 4) : f4all(c.x);
        }
        if (lane == 31) {
            r1 = (x0 + 4 < WW) ? p[4] : c.w;
            r4 = (x0 + 4 < WW) ? ld4(p + 4) : f4all(c.w);
        }

        float4 a;
        a.x = fmaf(s0, (u1.x + d1.x) + (l1  + c.y),
              fmaf(s1, (u4v.x + d4v.x) + (l4.x + r4.x),
              fmaf(s2, (u16.x + d16.x) + (l16.x + r16.x), sm4 * c.x)));
        a.y = fmaf(s0, (u1.y + d1.y) + (c.x + c.z),
              fmaf(s1, (u4v.y + d4v.y) + (l4.y + r4.y),
              fmaf(s2, (u16.y + d16.y) + (l16.y + r16.y), sm4 * c.y)));
        a.z = fmaf(s0, (u1.z + d1.z) + (c.y + c.w),
              fmaf(s1, (u4v.z + d4v.z) + (l4.z + r4.z),
              fmaf(s2, (u16.z + d16.z) + (l16.z + r16.z), sm4 * c.z)));
        a.w = fmaf(s0, (u1.w + d1.w) + (c.z + r1),
              fmaf(s1, (u4v.w + d4v.w) + (l4.w + r4.w),
              fmaf(s2, (u16.w + d16.w) + (l16.w + r16.w), sm4 * c.w)));

        *reinterpret_cast<float4*>(po + t * WW) = a;

        w0 = w1;
        w1 = w2;
        w2 = ld4(p + 2 * WW);
    }
}

// ---------------- edge kernel: full clamping, 2 y-blocks ----------------
__global__ __launch_bounds__(128, 8) void lap_edge(const float* __restrict__ u,
                                                   float* __restrict__ out) {
    const int lane = threadIdx.x;
    const int span = threadIdx.y;
    const int x0   = (span << 7) + (lane << 2);
    const int y0   = blockIdx.y ? (HH - RROWS) : 0;
    const int img  = blockIdx.z;
    const int ch   = img & (CC - 1);

    const float* __restrict__ base = u + (size_t)img * (HH * WW);
    float* __restrict__ ob = out + (size_t)img * (HH * WW);

    const float s0 = g_scales[ch];
    const float s1 = g_scales[64 + ch];
    const float s2 = g_scales[128 + ch];
    const float sm4 = -4.0f * (s0 + s1 + s2);
    const unsigned m = 0xFFFFFFFFu;

    float4 w0 = ld4(base + max(y0 - 1, 0) * WW + x0);
    float4 w1 = ld4(base + y0 * WW + x0);
    float4 w2 = ld4(base + min(y0 + 1, HH - 1) * WW + x0);

#pragma unroll
    for (int t = 0; t < RROWS; t++) {
        const int y = y0 + t;
        const float* __restrict__ rowc = base + y * WW;

        const float4 u4v = ld4(base + max(y - 4, 0) * WW + x0);
        const float4 d4v = ld4(base + min(y + 4, HH - 1) * WW + x0);
        const float4 u16 = ld4(base + max(y - 16, 0) * WW + x0);
        const float4 d16 = ld4(base + min(y + 16, HH - 1) * WW + x0);

        const float4 c  = w1;
        const float4 u1 = w0;
        const float4 d1 = w2;

        const float4 l16 = (x0 >= 16)     ? ld4(rowc + x0 - 16) : f4all(rowc[0]);
        const float4 r16 = (x0 + 16 < WW) ? ld4(rowc + x0 + 16) : f4all(rowc[WW - 1]);

        float4 l4, r4;
        l4.x = __shfl_up_sync(m, c.x, 1);
        l4.y = __shfl_up_sync(m, c.y, 1);
        l4.z = __shfl_up_sync(m, c.z, 1);
        l4.w = __shfl_up_sync(m, c.w, 1);
        r4.x = __shfl_down_sync(m, c.x, 1);
        r4.y = __shfl_down_sync(m, c.y, 1);
        r4.z = __shfl_down_sync(m, c.z, 1);
        r4.w = __shfl_down_sync(m, c.w, 1);

        float l1 = l4.w;
        float r1 = r4.x;
        if (lane == 0) {
            l1 = (x0 > 0) ? rowc[x0 - 1] : c.x;
            l4 = (x0 >= 4) ? ld4(rowc + x0 - 4) : f4all(c.x);
        }
        if (lane == 31) {
            r1 = (x0 + 4 < WW) ? rowc[x0 + 4] : c.w;
            r4 = (x0 + 4 < WW) ? ld4(rowc + x0 + 4) : f4all(c.w);
        }

        float4 a;
        a.x = fmaf(s0, (u1.x + d1.x) + (l1  + c.y),
              fmaf(s1, (u4v.x + d4v.x) + (l4.x + r4.x),
              fmaf(s2, (u16.x + d16.x) + (l16.x + r16.x), sm4 * c.x)));
        a.y = fmaf(s0, (u1.y + d1.y) + (c.x + c.z),
              fmaf(s1, (u4v.y + d4v.y) + (l4.y + r4.y),
              fmaf(s2, (u16.y + d16.y) + (l16.y + r16.y), sm4 * c.y)));
        a.z = fmaf(s0, (u1.z + d1.z) + (c.y + c.w),
              fmaf(s1, (u4v.z + d4v.z) + (l4.z + r4.z),
              fmaf(s2, (u16.z + d16.z) + (l16.z + r16.z), sm4 * c.z)));
        a.w = fmaf(s0, (u1.w + d1.w) + (c.z + r1),
              fmaf(s1, (u4v.w + d4v.w) + (l4.w + r4.w),
              fmaf(s2, (u16.w + d16.w) + (l16.w + r16.w), sm4 * c.w)));

        *reinterpret_cast<float4*>(ob + y * WW + x0) = a;

        w0 = w1;
        w1 = w2;
        w2 = ld4(base + min(y + 2, HH - 1) * WW + x0);
    }
}

extern "C" void kernel_launch(void* const* d_in, const int* in_sizes, int n_in,
                              void* d_out, int out_size) {
    const float* u;
    const float* D;
    int nu;
    if (in_sizes[0] > in_sizes[1]) {
        u = (const float*)d_in[0]; D = (const float*)d_in[1]; nu = in_sizes[0];
    } else {
        u = (const float*)d_in[1]; D = (const float*)d_in[0]; nu = in_sizes[1];
    }
    float* out = (float*)d_out;
    const int B = nu / (CC * HH * WW);

    softplus_kernel<<<1, 192>>>(D);

    dim3 blk(32, 4, 1);
    dim3 grd_i(1, HH / RROWS - 2, B * CC);   // 30 interior y-blocks
    dim3 grd_e(1, 2, B * CC);                // 2 edge y-blocks
    lap_interior<<<grd_i, blk>>>(u, out);
    lap_edge<<<grd_e, blk>>>(u, out);
}

// round 6
// speedup vs baseline: 1.5866x; 1.5866x over previous
#include <cuda_runtime.h>

#define HH 512
#define WW 512
#define CC 64
#define RROWS 16

__device__ float g_scales[192];

__global__ void softplus_kernel(const float* __restrict__ D) {
    int i = threadIdx.x;
    if (i < 192) {
        float x = D[i];
        g_scales[i] = (x > 20.0f) ? x : log1pf(expf(x));
    }
}

__device__ __forceinline__ float4 ld4(const float* __restrict__ p) {
    return *reinterpret_cast<const float4*>(p);
}
__device__ __forceinline__ float4 f4all(float v) {
    return make_float4(v, v, v, v);
}

__global__ __launch_bounds__(128, 9) void lap_kernel(const float* __restrict__ u,
                                                     float* __restrict__ out) {
    const int lane = threadIdx.x;                 // 0..31
    const int span = threadIdx.y;                 // 0..3
    const int x0   = (span << 7) + (lane << 2);   // this thread's float4 x
    const int y0   = blockIdx.y * RROWS;
    const int img  = blockIdx.z;
    const int ch   = img & (CC - 1);

    const float* __restrict__ base = u + (size_t)img * (HH * WW);
    float* __restrict__ ob = out + (size_t)img * (HH * WW);

    const float s0 = g_scales[ch];
    const float s1 = g_scales[64 + ch];
    const float s2 = g_scales[128 + ch];
    const float sm4 = -4.0f * (s0 + s1 + s2);
    const unsigned m = 0xFFFFFFFFu;

    // 3-row rolling window: w0=y-1, w1=y, w2=y+1
    float4 w0 = ld4(base + max(y0 - 1, 0) * WW + x0);
    float4 w1 = ld4(base + y0 * WW + x0);
    float4 w2 = ld4(base + min(y0 + 1, HH - 1) * WW + x0);

#pragma unroll 2
    for (int t = 0; t < RROWS; t++) {
        const int y = y0 + t;
        const float* __restrict__ rowc = base + y * WW;

        const float4 c = w1;
        float4 a;

        // ---- d=16 group: load, consume, release ----
        {
            const float4 u16 = ld4(base + max(y - 16, 0) * WW + x0);
            const float4 d16 = ld4(base + min(y + 16, HH - 1) * WW + x0);
            const float4 l16 = (x0 >= 16)     ? ld4(rowc + x0 - 16) : f4all(rowc[0]);
            const float4 r16 = (x0 + 16 < WW) ? ld4(rowc + x0 + 16) : f4all(rowc[WW - 1]);
            a.x = fmaf(s2, (u16.x + d16.x) + (l16.x + r16.x), sm4 * c.x);
            a.y = fmaf(s2, (u16.y + d16.y) + (l16.y + r16.y), sm4 * c.y);
            a.z = fmaf(s2, (u16.z + d16.z) + (l16.z + r16.z), sm4 * c.z);
            a.w = fmaf(s2, (u16.w + d16.w) + (l16.w + r16.w), sm4 * c.w);
        }

        // ---- d=4 group: vertical loads + horizontal shuffles ----
        float l1, r1;
        {
            const float4 u4v = ld4(base + max(y - 4, 0) * WW + x0);
            const float4 d4v = ld4(base + min(y + 4, HH - 1) * WW + x0);
            float4 l4, r4;
            l4.x = __shfl_up_sync(m, c.x, 1);
            l4.y = __shfl_up_sync(m, c.y, 1);
            l4.z = __shfl_up_sync(m, c.z, 1);
            l4.w = __shfl_up_sync(m, c.w, 1);
            r4.x = __shfl_down_sync(m, c.x, 1);
            r4.y = __shfl_down_sync(m, c.y, 1);
            r4.z = __shfl_down_sync(m, c.z, 1);
            r4.w = __shfl_down_sync(m, c.w, 1);

            // d=1 horizontal reuses lane-shift values before fixup
            l1 = l4.w;
            r1 = r4.x;
            if (lane == 0) {
                l1 = (x0 > 0) ? rowc[x0 - 1] : c.x;
                l4 = (x0 >= 4) ? ld4(rowc + x0 - 4) : f4all(c.x);
            }
            if (lane == 31) {
                r1 = (x0 + 4 < WW) ? rowc[x0 + 4] : c.w;
                r4 = (x0 + 4 < WW) ? ld4(rowc + x0 + 4) : f4all(c.w);
            }

            a.x = fmaf(s1, (u4v.x + d4v.x) + (l4.x + r4.x), a.x);
            a.y = fmaf(s1, (u4v.y + d4v.y) + (l4.y + r4.y), a.y);
            a.z = fmaf(s1, (u4v.z + d4v.z) + (l4.z + r4.z), a.z);
            a.w = fmaf(s1, (u4v.w + d4v.w) + (l4.w + r4.w), a.w);
        }

        // ---- d=1 group: from rolling window ----
        a.x = fmaf(s0, (w0.x + w2.x) + (l1  + c.y), a.x);
        a.y = fmaf(s0, (w0.y + w2.y) + (c.x + c.z), a.y);
        a.z = fmaf(s0, (w0.z + w2.z) + (c.y + c.w), a.z);
        a.w = fmaf(s0, (w0.w + w2.w) + (c.z + r1 ), a.w);

        *reinterpret_cast<float4*>(ob + y * WW + x0) = a;

        // roll window down one row
        w0 = w1;
        w1 = w2;
        w2 = ld4(base + min(y + 2, HH - 1) * WW + x0);
    }
}

extern "C" void kernel_launch(void* const* d_in, const int* in_sizes, int n_in,
                              void* d_out, int out_size) {
    const float* u;
    const float* D;
    int nu;
    if (in_sizes[0] > in_sizes[1]) {
        u = (const float*)d_in[0]; D = (const float*)d_in[1]; nu = in_sizes[0];
    } else {
        u = (const float*)d_in[1]; D = (const float*)d_in[0]; nu = in_sizes[1];
    }
    float* out = (float*)d_out;
    const int B = nu / (CC * HH * WW);

    softplus_kernel<<<1, 192>>>(D);

    dim3 blk(32, 4, 1);
    dim3 grd(1, HH / RROWS, B * CC);
    lap_kernel<<<grd, blk>>>(u, out);
}